// round 8
// baseline (speedup 1.0000x reference)
#include <cuda_runtime.h>
#include <cstdint>

// fired[pos, r] = f(x[pos,a]) * f(x[pos,5+b]) * f(x[pos,10+c]),
//   r = 25a + 5b + c,  f(v) = (v==0 ? 1 : v)
// Instruction-minimal warp-autonomous version:
//   - x staged RAW (flat 60 floats/warp, no deswizzle divisions)
//   - Phase A uses one LDS base per operand + immediate offsets
//   - output staged in smem, ONE cp.async.bulk smem->global per warp

#define F_DIM    15
#define R_DIM    125
#define NPAIR    25
#define WARPS    4
#define POS_PW   4                        // positions per warp
#define POS_PB   (WARPS * POS_PW)         // 16
#define NTHREADS (WARPS * 32)             // 128
#define WFLOATS  (POS_PW * R_DIM)         // 500 floats per warp
#define WBYTES   (WFLOATS * 4)            // 2000 B
#define WXVEC    ((POS_PW * F_DIM) / 4)   // 15 float4 x-loads per warp

__device__ __forceinline__ uint32_t smem_u32(const void* p) {
    return (uint32_t)__cvta_generic_to_shared(p);
}

__global__ __launch_bounds__(NTHREADS)
void rules_fired_kernel(const float* __restrict__ x,
                        float* __restrict__ out,
                        int n_pos)
{
    __shared__ __align__(16) float xs[WARPS][POS_PW * F_DIM + 4];  // flat, raw
    __shared__ __align__(16) float so[WARPS][WFLOATS];             // 8 KB

    const int w    = threadIdx.x >> 5;
    const int lane = threadIdx.x & 31;
    const long long wpos0 = (long long)blockIdx.x * POS_PB + w * POS_PW;
    const bool full = (wpos0 + POS_PW <= n_pos);

    // ── Phase 1: 15 lanes: LDG.128 -> select x4 -> STS.128 raw (flat).
    if (lane < WXVEC) {
        float4 v;
        if (full) {
            v = ((const float4*)(x + wpos0 * F_DIM))[lane];
        } else {
            float* ve = (float*)&v;
            const long long xtot = (long long)n_pos * F_DIM;
            #pragma unroll
            for (int k = 0; k < 4; k++) {
                long long gi = wpos0 * F_DIM + lane * 4 + k;
                ve[k] = (gi < xtot) ? x[gi] : 1.0f;
            }
        }
        if (v.x == 0.0f) v.x = 1.0f;
        if (v.y == 0.0f) v.y = 1.0f;
        if (v.z == 0.0f) v.z = 1.0f;
        if (v.w == 0.0f) v.w = 1.0f;
        ((float4*)xs[w])[lane] = v;
    }
    __syncwarp();

    // ── Phase A: lane = pair j = 5a+b (decode once); all smem addresses are
    //    one base register + compile-time immediate offsets.
    if (lane < NPAIR) {
        const int a = lane / 5;
        const int b = lane - a * 5;
        const float* xa = &xs[w][a];          // +p*15 immediates
        const float* xb = &xs[w][5 + b];
        const float* xw = &xs[w][0];          // xc at +p*15+10+c immediates
        float* dst = &so[w][lane * 5];        // +p*125+c immediates (bank-clean)
        #pragma unroll
        for (int p = 0; p < POS_PW; p++) {
            const float pab = xa[p * F_DIM] * xb[p * F_DIM];
            #pragma unroll
            for (int c = 0; c < 5; c++)
                dst[p * R_DIM + c] = pab * xw[p * F_DIM + 10 + c];
        }
    }
    __syncwarp();

    // ── Phase B: one bulk async copy smem -> global (2000 B) per warp.
    if (full) {
        if (lane == 0) {
            asm volatile("fence.proxy.async.shared::cta;" ::: "memory");
            uint32_t saddr = smem_u32(&so[w][0]);
            float* gdst = out + wpos0 * R_DIM;
            asm volatile(
                "cp.async.bulk.global.shared::cta.bulk_group [%0], [%1], %2;"
                :: "l"(gdst), "r"(saddr), "n"(WBYTES) : "memory");
            asm volatile("cp.async.bulk.commit_group;" ::: "memory");
            asm volatile("cp.async.bulk.wait_group 0;" ::: "memory");
        }
    } else {
        const long long total = (long long)n_pos * R_DIM;
        for (int i = lane; i < WFLOATS; i += 32) {
            long long gi = wpos0 * R_DIM + i;
            if (gi < total) out[gi] = so[w][i];
        }
    }
}

extern "C" void kernel_launch(void* const* d_in, const int* in_sizes, int n_in,
                              void* d_out, int out_size)
{
    const float* x = (const float*)d_in[0];   // (B, S, F) float32
    // d_in[1] = active_rules (structurally fixed one-hot; decode hardcoded)
    // d_in[2] = epoch (unused)
    float* out = (float*)d_out;               // (B, S, R) float32

    const int n_pos    = in_sizes[0] / F_DIM;                 // 32768
    const int n_blocks = (n_pos + POS_PB - 1) / POS_PB;       // 2048

    rules_fired_kernel<<<n_blocks, NTHREADS>>>(x, out, n_pos);
}